// round 6
// baseline (speedup 1.0000x reference)
#include <cuda_runtime.h>
#include <cstdint>

#define BATCH 4
#define SEQ   2048
#define DIN   128
#define HDIM  64
#define ROWS  (BATCH*SEQ)        // 8192
#define TQ    64                 // q rows per block in k_attn2
#define KT    128                // k cols per tile
#define NKB   (SEQ/KT)           // 16

// ---- device scratch (no allocations allowed) ----
__device__ float g_q [ROWS*HDIM];
__device__ float g_kT[BATCH*HDIM*SEQ];   // k projected, transposed: [b][h][s]
__device__ float g_v [ROWS*HDIM];
__device__ float g_q2[ROWS];
__device__ float g_k2[ROWS];
__device__ float g_ctx[ROWS*HDIM];       // normalized ctx
__device__ float g_outs[ROWS*HDIM];      // fallback out scratch

// ================= cp.async helpers =================
__device__ __forceinline__ void cpa16(void* dst_smem, const void* src) {
    unsigned d = (unsigned)__cvta_generic_to_shared(dst_smem);
    asm volatile("cp.async.cg.shared.global [%0], [%1], 16;\n" :: "r"(d), "l"(src));
}
#define CP_COMMIT() asm volatile("cp.async.commit_group;\n")
#define CP_WAIT(N)  asm volatile("cp.async.wait_group %0;\n" :: "n"(N))

// ================= tf32 mma + split =================
__device__ __forceinline__ float tf32_rna(float x) {
    uint32_t r; asm("cvt.rna.tf32.f32 %0, %1;\n" : "=r"(r) : "f"(x));
    return __uint_as_float(r);
}
__device__ __forceinline__ void mma_tf32(float& d0, float& d1, float& d2, float& d3,
                                         float a0, float a1, float a2, float a3,
                                         float b0, float b1)
{
    asm volatile(
        "mma.sync.aligned.m16n8k8.row.col.f32.tf32.tf32.f32 "
        "{%0,%1,%2,%3}, {%4,%5,%6,%7}, {%8,%9}, {%0,%1,%2,%3};\n"
        : "+f"(d0), "+f"(d1), "+f"(d2), "+f"(d3)
        : "r"(__float_as_uint(a0)), "r"(__float_as_uint(a1)),
          "r"(__float_as_uint(a2)), "r"(__float_as_uint(a3)),
          "r"(__float_as_uint(b0)), "r"(__float_as_uint(b1)));
}
// 3xTF32: acc += a*b with near-fp32 precision (Dekker split, drop small*small)
__device__ __forceinline__ void mma3_tf32(float* acc,
    float ab0, float ab1, float ab2, float ab3,
    float as0, float as1, float as2, float as3,
    float b0, float b1)
{
    float bb0 = tf32_rna(b0), bb1 = tf32_rna(b1);
    float bs0 = b0 - bb0,     bs1 = b1 - bb1;
    mma_tf32(acc[0], acc[1], acc[2], acc[3], ab0, ab1, ab2, ab3, bb0, bb1);
    mma_tf32(acc[0], acc[1], acc[2], acc[3], ab0, ab1, ab2, ab3, bs0, bs1);
    mma_tf32(acc[0], acc[1], acc[2], acc[3], as0, as1, as2, as3, bb0, bb1);
}

// ================= projections: y = X @ W + b, plus rownorm^2 =================
// 64 rows per block, grid (ROWS/64, 3)
__global__ __launch_bounds__(256) void k_proj(
    const float* __restrict__ qs, const float* __restrict__ ks, const float* __restrict__ vs,
    const float* __restrict__ Wq, const float* __restrict__ bq,
    const float* __restrict__ Wk, const float* __restrict__ bk,
    const float* __restrict__ Wv, const float* __restrict__ bv)
{
    const float* X; const float* W; const float* bias; float* Y; float* sq;
    int mode = blockIdx.y;
    switch (mode) {
        case 0:  X = qs; W = Wq; bias = bq; Y = g_q;  sq = g_q2; break;
        case 1:  X = ks; W = Wk; bias = bk; Y = nullptr; sq = g_k2; break;
        default: X = vs; W = Wv; bias = bv; Y = g_v;  sq = nullptr; break;
    }
    __shared__ float Xs[32][68];    // X tile transposed [d][row(64)], padded
    __shared__ float Ws[32][68];    // W tile [d][h]

    int tid = threadIdx.x;
    int hg = tid & 7;        // 8 h-groups (8 cols each)
    int rg = tid >> 3;       // 32 row-groups (2 rows each)
    int row0 = blockIdx.x * 64;

    float acc[2][8];
    #pragma unroll
    for (int i = 0; i < 2; i++)
        #pragma unroll
        for (int j = 0; j < 8; j++) acc[i][j] = 0.f;

    for (int d0 = 0; d0 < DIN; d0 += 32) {
        #pragma unroll
        for (int it = 0; it < 2; it++) {               // 64 rows x 32 d = 512 float4
            int f4 = it * 256 + tid;
            int r = f4 >> 3, d4 = (f4 & 7) * 4;
            float4 x = *(const float4*)&X[(size_t)(row0 + r) * DIN + d0 + d4];
            Xs[d4 + 0][r] = x.x; Xs[d4 + 1][r] = x.y;
            Xs[d4 + 2][r] = x.z; Xs[d4 + 3][r] = x.w;
        }
        #pragma unroll
        for (int it = 0; it < 2; it++) {               // 32 d x 64 h = 512 float4
            int f4 = it * 256 + tid;
            int dk = f4 >> 4, h4 = (f4 & 15) * 4;
            *(float4*)&Ws[dk][h4] = *(const float4*)&W[(d0 + dk) * HDIM + h4];
        }
        __syncthreads();
        #pragma unroll
        for (int dk = 0; dk < 32; dk++) {
            float2 xa = *(float2*)&Xs[dk][rg * 2];
            float4 w0 = *(float4*)&Ws[dk][hg * 8];
            float4 w1 = *(float4*)&Ws[dk][hg * 8 + 4];
            float xf[2] = {xa.x, xa.y};
            float wf[8] = {w0.x, w0.y, w0.z, w0.w, w1.x, w1.y, w1.z, w1.w};
            #pragma unroll
            for (int i = 0; i < 2; i++)
                #pragma unroll
                for (int j = 0; j < 8; j++) acc[i][j] += xf[i] * wf[j];
        }
        __syncthreads();
    }

    float bb[8];
    #pragma unroll
    for (int j = 0; j < 8; j++) bb[j] = bias[hg * 8 + j];

    #pragma unroll
    for (int i = 0; i < 2; i++) {
        int row = row0 + rg * 2 + i;
        float y[8]; float p = 0.f;
        #pragma unroll
        for (int j = 0; j < 8; j++) { y[j] = acc[i][j] + bb[j]; p += y[j] * y[j]; }
        if (mode == 1) {
            int b = row >> 11;
            int s = row & (SEQ - 1);
            #pragma unroll
            for (int j = 0; j < 8; j++)
                g_kT[((size_t)b * HDIM + hg * 8 + j) * SEQ + s] = y[j];
        } else {
            *(float4*)&Y[(size_t)row * HDIM + hg * 8]     = make_float4(y[0], y[1], y[2], y[3]);
            *(float4*)&Y[(size_t)row * HDIM + hg * 8 + 4] = make_float4(y[4], y[5], y[6], y[7]);
        }
        p += __shfl_xor_sync(0xffffffffu, p, 4);
        p += __shfl_xor_sync(0xffffffffu, p, 2);
        p += __shfl_xor_sync(0xffffffffu, p, 1);
        if (sq && hg == 0) sq[row] = p;
    }
}

// ======== fused attention: 512 threads, per 64-q-row block over all 2048 k ==========
#define OFF_QS   0
#define OFF_KS0  (OFF_QS  + 64*68)
#define OFF_KS1  (OFF_KS0 + 64*136)
#define OFF_VS0  (OFF_KS1 + 64*136)
#define OFF_VS1  (OFF_VS0 + 128*72)
#define OFF_K20  (OFF_VS1 + 128*72)
#define OFF_K21  (OFF_K20 + 128)
#define OFF_SS   (OFF_K21 + 128)
#define OFF_RED  (OFF_SS  + 64*132)
#define SMEM_FLOATS (OFF_RED + 256 + 64)
#define SMEM_BYTES  (SMEM_FLOATS * 4)

__global__ __launch_bounds__(512, 1) void k_attn2(float* __restrict__ attn, int do_attn)
{
    extern __shared__ float sm[];
    float* Qs  = sm + OFF_QS;
    float* KsB[2] = { sm + OFF_KS0, sm + OFF_KS1 };
    float* VsB[2] = { sm + OFF_VS0, sm + OFF_VS1 };
    float* k2B[2] = { sm + OFF_K20, sm + OFF_K21 };
    float* Ss  = sm + OFF_SS;
    float* red = sm + OFF_RED;           // [4][64] partials
    float* rinv = red + 256;             // [64]

    const int tid  = threadIdx.x;
    const int lane = tid & 31;
    const int wid  = tid >> 5;           // 0..15
    const int g    = lane >> 2;
    const int tig  = lane & 3;
    const int wm   = wid & 3;            // 4 m-tiles of 16 rows
    const int wn   = wid >> 2;           // 4 n-groups

    const int row0 = blockIdx.x * TQ;
    const int b    = row0 >> 11;
    const float* kT_base = g_kT + (size_t)b * HDIM * SEQ;
    const float* v_base  = g_v  + (size_t)b * SEQ * HDIM;
    const float* k2_base = g_k2 + b * SEQ;

    // ---- prologue staging ----
    #pragma unroll
    for (int it = 0; it < 2; it++) {                 // Q: 1024 x 16B
        int op = it * 512 + tid;
        int r = op >> 4, c = (op & 15) * 4;
        cpa16(&Qs[r * 68 + c], &g_q[(size_t)(row0 + r) * HDIM + c]);
    }
    #pragma unroll
    for (int it = 0; it < 4; it++) {                 // K: 2048 x 16B
        int op = it * 512 + tid;
        int h = op >> 5, c = (op & 31) * 4;
        cpa16(&KsB[0][h * 136 + c], kT_base + (size_t)h * SEQ + c);
    }
    #pragma unroll
    for (int it = 0; it < 4; it++) {                 // V: 2048 x 16B
        int op = it * 512 + tid;
        int r = op >> 4, c = (op & 15) * 4;
        cpa16(&VsB[0][r * 72 + c], v_base + (size_t)r * HDIM + c);
    }
    if (tid < 32) cpa16(&k2B[0][tid * 4], k2_base + tid * 4);
    CP_COMMIT();

    float q2r0 = g_q2[row0 + wm * 16 + g];
    float q2r1 = g_q2[row0 + wm * 16 + g + 8];
    float rs0 = 0.f, rs1 = 0.f;
    float cacc[2][4];
    #pragma unroll
    for (int i = 0; i < 2; i++)
        #pragma unroll
        for (int j = 0; j < 4; j++) cacc[i][j] = 0.f;

    for (int kb = 0; kb < NKB; kb++) {
        const int bf = kb & 1;
        if (kb + 1 < NKB) {
            const int nb = (kb + 1) & 1;
            const float* kTn = kT_base + (kb + 1) * KT;
            const float* vn  = v_base + (size_t)(kb + 1) * KT * HDIM;
            #pragma unroll
            for (int it = 0; it < 4; it++) {
                int op = it * 512 + tid;
                int h = op >> 5, c = (op & 31) * 4;
                cpa16(&KsB[nb][h * 136 + c], kTn + (size_t)h * SEQ + c);
            }
            #pragma unroll
            for (int it = 0; it < 4; it++) {
                int op = it * 512 + tid;
                int r = op >> 4, c = (op & 15) * 4;
                cpa16(&VsB[nb][r * 72 + c], vn + (size_t)r * HDIM + c);
            }
            if (tid < 32) cpa16(&k2B[nb][tid * 4], k2_base + (kb + 1) * KT + tid * 4);
            CP_COMMIT();
            CP_WAIT(1);
        } else {
            CP_WAIT(0);
        }
        __syncthreads();

        float* Ks = KsB[bf];
        float* Vs = VsB[bf];
        float* k2s = k2B[bf];

        // ---- scores: 64q x 128k, warp grid 4m x 4n, warp tile 16x32 ----
        float sacc[4][4];
        #pragma unroll
        for (int i = 0; i < 4; i++)
            #pragma unroll
            for (int j = 0; j < 4; j++) sacc[i][j] = 0.f;

        #pragma unroll
        for (int kk = 0; kk < 8; kk++) {
            int ar = (wm * 16 + g) * 68 + kk * 8 + tig;
            float a0 = Qs[ar];
            float a1 = Qs[ar + 8 * 68];
            float a2 = Qs[ar + 4];
            float a3 = Qs[ar + 8 * 68 + 4];
            float ab0 = tf32_rna(a0), ab1 = tf32_rna(a1), ab2 = tf32_rna(a2), ab3 = tf32_rna(a3);
            float as0 = a0 - ab0, as1 = a1 - ab1, as2 = a2 - ab2, as3 = a3 - ab3;
            #pragma unroll
            for (int nt = 0; nt < 4; nt++) {
                int n0 = wn * 32 + nt * 8;
                float b0 = Ks[(kk * 8 + tig) * 136 + n0 + g];
                float b1 = Ks[(kk * 8 + tig + 4) * 136 + n0 + g];
                mma3_tf32(sacc[nt], ab0, ab1, ab2, ab3, as0, as1, as2, as3, b0, b1);
            }
        }

        // ---- exp + rowsum + store S to smem ----
        #pragma unroll
        for (int nt = 0; nt < 4; nt++) {
            int cg = wn * 32 + nt * 8 + 2 * tig;
            float2 k2p = *(float2*)&k2s[cg];
            float e00 = __expf(-0.125f * (q2r0 + k2p.x - 2.f * sacc[nt][0]));
            float e01 = __expf(-0.125f * (q2r0 + k2p.y - 2.f * sacc[nt][1]));
            float e10 = __expf(-0.125f * (q2r1 + k2p.x - 2.f * sacc[nt][2]));
            float e11 = __expf(-0.125f * (q2r1 + k2p.y - 2.f * sacc[nt][3]));
            rs0 += e00 + e01;
            rs1 += e10 + e11;
            int r = wm * 16 + g;
            *(float2*)&Ss[r * 132 + cg]       = make_float2(e00, e01);
            *(float2*)&Ss[(r + 8) * 132 + cg] = make_float2(e10, e11);
        }
        __syncthreads();

        // ---- write unnormalized attn tile ----
        if (do_attn) {
            #pragma unroll
            for (int it = 0; it < 4; it++) {
                int f = it * 512 + tid;
                int r = f >> 5, c4 = (f & 31) * 4;
                float4 v4 = *(float4*)&Ss[r * 132 + c4];
                *(float4*)&attn[(size_t)(row0 + r) * SEQ + kb * KT + c4] = v4;
            }
        }

        // ---- ctx accumulate: 64q x 64h, warp grid 4m x 4n, warp tile 16x16 ----
        #pragma unroll
        for (int kk = 0; kk < 16; kk++) {
            int ar = (wm * 16 + g) * 132 + kk * 8 + tig;
            float a0 = Ss[ar];
            float a1 = Ss[ar + 8 * 132];
            float a2 = Ss[ar + 4];
            float a3 = Ss[ar + 8 * 132 + 4];
            float ab0 = tf32_rna(a0), ab1 = tf32_rna(a1), ab2 = tf32_rna(a2), ab3 = tf32_rna(a3);
            float as0 = a0 - ab0, as1 = a1 - ab1, as2 = a2 - ab2, as3 = a3 - ab3;
            #pragma unroll
            for (int nt = 0; nt < 2; nt++) {
                int n0 = wn * 16 + nt * 8;
                float b0 = Vs[(kk * 8 + tig) * 72 + n0 + g];
                float b1 = Vs[(kk * 8 + tig + 4) * 72 + n0 + g];
                mma3_tf32(cacc[nt], ab0, ab1, ab2, ab3, as0, as1, as2, as3, b0, b1);
            }
        }
        __syncthreads();
    }

    // ---- rowsum reduce (each warp covered 32 cols; 4 wn groups per row) ----
    rs0 += __shfl_xor_sync(0xffffffffu, rs0, 1);
    rs0 += __shfl_xor_sync(0xffffffffu, rs0, 2);
    rs1 += __shfl_xor_sync(0xffffffffu, rs1, 1);
    rs1 += __shfl_xor_sync(0xffffffffu, rs1, 2);
    if (tig == 0) {
        red[wn * 64 + wm * 16 + g]     = rs0;
        red[wn * 64 + wm * 16 + g + 8] = rs1;
    }
    __syncthreads();
    if (tid < 64)
        rinv[tid] = 1.0f / (red[tid] + red[64 + tid] + red[128 + tid] + red[192 + tid]);
    __syncthreads();

    // ---- write normalized ctx ----
    {
        float ri0 = rinv[wm * 16 + g];
        float ri1 = rinv[wm * 16 + g + 8];
        int r0_ = row0 + wm * 16 + g;
        #pragma unroll
        for (int nt = 0; nt < 2; nt++) {
            int col = wn * 16 + nt * 8 + 2 * tig;
            *(float2*)&g_ctx[(size_t)r0_ * HDIM + col] =
                make_float2(cacc[nt][0] * ri0, cacc[nt][1] * ri0);
            *(float2*)&g_ctx[(size_t)(r0_ + 8) * HDIM + col] =
                make_float2(cacc[nt][2] * ri1, cacc[nt][3] * ri1);
        }
    }

    // ---- normalize attn in place (tiles likely L2-resident) ----
    if (do_attn) {
        for (int kb = 0; kb < NKB; kb++) {
            #pragma unroll
            for (int it = 0; it < 4; it++) {
                int f = it * 512 + tid;
                int r = f >> 5, c4 = (f & 31) * 4;
                float ri = rinv[r];
                float* p = &attn[(size_t)(row0 + r) * SEQ + kb * KT + c4];
                float4 v4 = *(float4*)p;
                v4.x *= ri; v4.y *= ri; v4.z *= ri; v4.w *= ri;
                *(float4*)p = v4;
            }
        }
    }
}

// ============== out = ctx @ Wo + bo (ctx already normalized) ==============
__global__ __launch_bounds__(256) void k_out(
    const float* __restrict__ Wo, const float* __restrict__ bo, float* __restrict__ out)
{
    __shared__ float cs[4][64];
    int tid = threadIdx.x;
    int r = tid >> 6, h = tid & 63;
    int row = blockIdx.x * 4 + r;
    cs[r][h] = g_ctx[(size_t)row * HDIM + h];
    __syncthreads();
    float o = bo[h];
    #pragma unroll 16
    for (int hp = 0; hp < HDIM; hp++) o += cs[r][hp] * Wo[hp * HDIM + h];
    out[(size_t)row * HDIM + h] = o;
}

// =========================== launch ===========================
extern "C" void kernel_launch(void* const* d_in, const int* in_sizes, int n_in,
                              void* d_out, int out_size)
{
    const float* qs = (const float*)d_in[0];
    const float* ks = (const float*)d_in[1];
    const float* vs = (const float*)d_in[2];
    const float* Wq = (const float*)d_in[3];
    const float* bq = (const float*)d_in[4];
    const float* Wk = (const float*)d_in[5];
    const float* bk = (const float*)d_in[6];
    const float* Wv = (const float*)d_in[7];
    const float* bv = (const float*)d_in[8];
    const float* Wo = (const float*)d_in[9];
    const float* bo = (const float*)d_in[10];

    const int OUTN = ROWS * HDIM;        // 524288
    const int ATTN = ROWS * SEQ;         // 16777216

    float* souts = nullptr;
    cudaGetSymbolAddress((void**)&souts, g_outs);

    float* outp; float* attnp;
    if (out_size >= OUTN + ATTN)      { outp = (float*)d_out; attnp = (float*)d_out + OUTN; }
    else if (out_size == ATTN)        { outp = souts;         attnp = (float*)d_out; }
    else                              { outp = (float*)d_out; attnp = nullptr; }

    cudaFuncSetAttribute(k_attn2, cudaFuncAttributeMaxDynamicSharedMemorySize, SMEM_BYTES);

    k_proj<<<dim3(ROWS / 64, 3), 256>>>(qs, ks, vs, Wq, bq, Wk, bk, Wv, bv);
    k_attn2<<<ROWS / TQ, 512, SMEM_BYTES>>>(attnp ? attnp : (float*)d_out,
                                            attnp != nullptr ? 1 : 0);
    k_out<<<ROWS / 4, 256>>>(Wo, bo, outp);
}

// round 9
// speedup vs baseline: 1.2811x; 1.2811x over previous
#include <cuda_runtime.h>
#include <cstdint>

#define BATCH 4
#define SEQ   2048
#define DIN   128
#define HDIM  64
#define ROWS  (BATCH*SEQ)        // 8192
#define TQ    64
#define KT    128
#define NKB   (SEQ/KT)           // 16

// ---- device scratch ----
__device__ float g_q [ROWS*HDIM];
__device__ float g_k [ROWS*HDIM];    // row-major (no transposed copy)
__device__ float g_v [ROWS*HDIM];
__device__ float g_q2[ROWS];
__device__ float g_k2[ROWS];
__device__ float g_ctx[ROWS*HDIM];
__device__ float g_outs[ROWS*HDIM];

// ================= cp.async helpers =================
__device__ __forceinline__ void cpa16(void* dst_smem, const void* src) {
    unsigned d = (unsigned)__cvta_generic_to_shared(dst_smem);
    asm volatile("cp.async.cg.shared.global [%0], [%1], 16;\n" :: "r"(d), "l"(src));
}
#define CP_COMMIT() asm volatile("cp.async.commit_group;\n")
#define CP_WAIT(N)  asm volatile("cp.async.wait_group %0;\n" :: "n"(N))

// ================= tf32 mma + split =================
__device__ __forceinline__ float tf32_rna(float x) {
    uint32_t r; asm("cvt.rna.tf32.f32 %0, %1;\n" : "=r"(r) : "f"(x));
    return __uint_as_float(r);
}
__device__ __forceinline__ void mma_tf32(float& d0, float& d1, float& d2, float& d3,
                                         float a0, float a1, float a2, float a3,
                                         float b0, float b1)
{
    asm volatile(
        "mma.sync.aligned.m16n8k8.row.col.f32.tf32.tf32.f32 "
        "{%0,%1,%2,%3}, {%4,%5,%6,%7}, {%8,%9}, {%0,%1,%2,%3};\n"
        : "+f"(d0), "+f"(d1), "+f"(d2), "+f"(d3)
        : "r"(__float_as_uint(a0)), "r"(__float_as_uint(a1)),
          "r"(__float_as_uint(a2)), "r"(__float_as_uint(a3)),
          "r"(__float_as_uint(b0)), "r"(__float_as_uint(b1)));
}
__device__ __forceinline__ void mma3_tf32(float* acc,
    float ab0, float ab1, float ab2, float ab3,
    float as0, float as1, float as2, float as3,
    float b0, float b1)
{
    float bb0 = tf32_rna(b0), bb1 = tf32_rna(b1);
    float bs0 = b0 - bb0,     bs1 = b1 - bb1;
    mma_tf32(acc[0], acc[1], acc[2], acc[3], ab0, ab1, ab2, ab3, bb0, bb1);
    mma_tf32(acc[0], acc[1], acc[2], acc[3], ab0, ab1, ab2, ab3, bs0, bs1);
    mma_tf32(acc[0], acc[1], acc[2], acc[3], as0, as1, as2, as3, bb0, bb1);
}

// ================= projections via tensor cores (3xTF32) =================
#define PJ_WS (64*132)
#define PJ_SQ (PJ_WS + 128*72)
#define PJ_BYTES ((PJ_SQ + 128) * 4)

__global__ __launch_bounds__(256) void k_proj(
    const float* __restrict__ qs, const float* __restrict__ ks, const float* __restrict__ vs,
    const float* __restrict__ Wq, const float* __restrict__ bq,
    const float* __restrict__ Wk, const float* __restrict__ bk,
    const float* __restrict__ Wv, const float* __restrict__ bv)
{
    extern __shared__ float psm[];
    float* Xs  = psm;            // [64][132]
    float* Ws  = psm + PJ_WS;    // [128][72]
    float* sqp = psm + PJ_SQ;    // [2][64]

    const float* X; const float* W; const float* bias; float* Y; float* sq;
    int mode = blockIdx.y;
    switch (mode) {
        case 0:  X = qs; W = Wq; bias = bq; Y = g_q; sq = g_q2; break;
        case 1:  X = ks; W = Wk; bias = bk; Y = g_k; sq = g_k2; break;
        default: X = vs; W = Wv; bias = bv; Y = g_v; sq = nullptr; break;
    }
    const int tid  = threadIdx.x;
    const int lane = tid & 31;
    const int wid  = tid >> 5;
    const int g    = lane >> 2;
    const int tig  = lane & 3;
    const int wm   = wid & 3;
    const int wn   = wid >> 2;
    const int row0 = blockIdx.x * 64;

    #pragma unroll
    for (int it = 0; it < 8; it++) {
        int op = it * 256 + tid;
        int r = op >> 5, c = (op & 31) * 4;
        cpa16(&Xs[r * 132 + c], &X[(size_t)(row0 + r) * DIN + c]);
    }
    #pragma unroll
    for (int it = 0; it < 8; it++) {
        int op = it * 256 + tid;
        int r = op >> 4, c = (op & 15) * 4;
        cpa16(&Ws[r * 72 + c], &W[(size_t)r * HDIM + c]);
    }
    CP_COMMIT(); CP_WAIT(0);
    __syncthreads();

    float acc[4][4];
    #pragma unroll
    for (int i = 0; i < 4; i++)
        #pragma unroll
        for (int j = 0; j < 4; j++) acc[i][j] = 0.f;

    #pragma unroll
    for (int kk = 0; kk < 16; kk++) {
        int ar = (wm * 16 + g) * 132 + kk * 8 + tig;
        float a0 = Xs[ar], a1 = Xs[ar + 8 * 132], a2 = Xs[ar + 4], a3 = Xs[ar + 8 * 132 + 4];
        float ab0 = tf32_rna(a0), ab1 = tf32_rna(a1), ab2 = tf32_rna(a2), ab3 = tf32_rna(a3);
        float as0 = a0 - ab0, as1 = a1 - ab1, as2 = a2 - ab2, as3 = a3 - ab3;
        #pragma unroll
        for (int nt = 0; nt < 4; nt++) {
            int br = (kk * 8 + tig) * 72 + wn * 32 + nt * 8 + g;
            float b0 = Ws[br], b1 = Ws[br + 4 * 72];
            mma3_tf32(acc[nt], ab0, ab1, ab2, ab3, as0, as1, as2, as3, b0, b1);
        }
    }

    float p0 = 0.f, p1 = 0.f;
    #pragma unroll
    for (int nt = 0; nt < 4; nt++) {
        int c = wn * 32 + nt * 8 + 2 * tig;
        float2 bb = *(const float2*)&bias[c];
        float y00 = acc[nt][0] + bb.x, y01 = acc[nt][1] + bb.y;
        float y10 = acc[nt][2] + bb.x, y11 = acc[nt][3] + bb.y;
        p0 += y00 * y00 + y01 * y01;
        p1 += y10 * y10 + y11 * y11;
        int r = row0 + wm * 16 + g;
        *(float2*)&Y[(size_t)r * HDIM + c]       = make_float2(y00, y01);
        *(float2*)&Y[(size_t)(r + 8) * HDIM + c] = make_float2(y10, y11);
    }
    if (sq) {
        p0 += __shfl_xor_sync(0xffffffffu, p0, 1);
        p0 += __shfl_xor_sync(0xffffffffu, p0, 2);
        p1 += __shfl_xor_sync(0xffffffffu, p1, 1);
        p1 += __shfl_xor_sync(0xffffffffu, p1, 2);
        if (tig == 0) {
            sqp[wn * 64 + wm * 16 + g]     = p0;
            sqp[wn * 64 + wm * 16 + g + 8] = p1;
        }
        __syncthreads();
        if (tid < 64) sq[row0 + tid] = sqp[tid] + sqp[64 + tid];
    }
}

// ======== fused attention: 256 threads, 8 warps (4m x 2n), TQ=64 over all k ========
#define OFF_KS0  0
#define OFF_KS1  (OFF_KS0 + 128*76)
#define OFF_VS0  (OFF_KS1 + 128*76)
#define OFF_VS1  (OFF_VS0 + 128*72)
#define OFF_K20  (OFF_VS1 + 128*72)
#define OFF_K21  (OFF_K20 + 128)
#define OFF_RED  (OFF_K21 + 128)
#define OFF_RINV (OFF_RED + 128)
#define OFF_CT   (OFF_RINV + 64)
#define SMEM_FLOATS (OFF_CT + 64*68)
#define SMEM_BYTES  (SMEM_FLOATS * 4)   // 170752

__global__ __launch_bounds__(256, 1) void k_attn2(float* __restrict__ attn, int do_attn)
{
    extern __shared__ float sm[];
    float* KsB[2] = { sm + OFF_KS0, sm + OFF_KS1 };   // [s(128)][h] stride 76
    float* VsB[2] = { sm + OFF_VS0, sm + OFF_VS1 };   // [s(128)][h] stride 72
    float* k2B[2] = { sm + OFF_K20, sm + OFF_K21 };
    float* red  = sm + OFF_RED;
    float* rinv = sm + OFF_RINV;
    float* ctmp = sm + OFF_CT;                        // [64][68]

    const int tid  = threadIdx.x;
    const int lane = tid & 31;
    const int wid  = tid >> 5;
    const int g    = lane >> 2;
    const int tig  = lane & 3;
    const int wm   = wid & 3;
    const int wn   = wid >> 2;

    const int row0 = blockIdx.x * TQ;
    const int b    = row0 >> 11;
    const float* k_base  = g_k  + (size_t)b * SEQ * HDIM;
    const float* v_base  = g_v  + (size_t)b * SEQ * HDIM;
    const float* k2_base = g_k2 + b * SEQ;

    float qA[8][4];
    {
        const float* qr0 = &g_q[(size_t)(row0 + wm * 16 + g) * HDIM];
        const float* qr1 = qr0 + 8 * HDIM;
        #pragma unroll
        for (int kk = 0; kk < 8; kk++) {
            qA[kk][0] = qr0[kk * 8 + tig];
            qA[kk][1] = qr1[kk * 8 + tig];
            qA[kk][2] = qr0[kk * 8 + tig + 4];
            qA[kk][3] = qr1[kk * 8 + tig + 4];
        }
    }
    float q2r0 = g_q2[row0 + wm * 16 + g];
    float q2r1 = g_q2[row0 + wm * 16 + g + 8];

    #pragma unroll
    for (int it = 0; it < 8; it++) {
        int op = it * 256 + tid;
        int r = op >> 4, c = (op & 15) * 4;
        cpa16(&KsB[0][r * 76 + c], k_base + (size_t)r * HDIM + c);
        cpa16(&VsB[0][r * 72 + c], v_base + (size_t)r * HDIM + c);
    }
    if (tid < 32) cpa16(&k2B[0][tid * 4], k2_base + tid * 4);
    CP_COMMIT();

    float rs0 = 0.f, rs1 = 0.f;
    float cacc[8][4];
    #pragma unroll
    for (int i = 0; i < 8; i++)
        #pragma unroll
        for (int j = 0; j < 4; j++) cacc[i][j] = 0.f;

    const int srcA = (lane & ~3) | (tig >> 1);
    const int srcB = srcA + 2;
    const bool odd = (tig & 1);

    for (int kb = 0; kb < NKB; kb++) {
        const int bf = kb & 1;
        if (kb + 1 < NKB) {
            const int nb = (kb + 1) & 1;
            const float* kn = k_base + (size_t)(kb + 1) * KT * HDIM;
            const float* vn = v_base + (size_t)(kb + 1) * KT * HDIM;
            #pragma unroll
            for (int it = 0; it < 8; it++) {
                int op = it * 256 + tid;
                int r = op >> 4, c = (op & 15) * 4;
                cpa16(&KsB[nb][r * 76 + c], kn + (size_t)r * HDIM + c);
                cpa16(&VsB[nb][r * 72 + c], vn + (size_t)r * HDIM + c);
            }
            if (tid < 32) cpa16(&k2B[nb][tid * 4], k2_base + (kb + 1) * KT + tid * 4);
            CP_COMMIT();
            CP_WAIT(1);
        } else {
            CP_WAIT(0);
        }
        __syncthreads();

        const float* Ks  = KsB[bf];
        const float* Vs  = VsB[bf];
        const float* k2s = k2B[bf];

        float e[8][4];
        #pragma unroll
        for (int nt = 0; nt < 8; nt++) {
            e[nt][0] = 0.f; e[nt][1] = 0.f; e[nt][2] = 0.f; e[nt][3] = 0.f;
        }
        #pragma unroll
        for (int kk = 0; kk < 8; kk++) {
            #pragma unroll
            for (int nt = 0; nt < 8; nt++) {
                int br = (wn * 64 + nt * 8 + g) * 76 + kk * 8 + tig;
                float b0 = Ks[br], b1 = Ks[br + 4];
                mma_tf32(e[nt][0], e[nt][1], e[nt][2], e[nt][3],
                         qA[kk][0], qA[kk][1], qA[kk][2], qA[kk][3], b0, b1);
            }
        }

        #pragma unroll
        for (int nt = 0; nt < 8; nt++) {
            int cg = wn * 64 + nt * 8 + 2 * tig;
            float2 k2p = *(const float2*)&k2s[cg];
            float e00 = __expf(-0.125f * (q2r0 + k2p.x - 2.f * e[nt][0]));
            float e01 = __expf(-0.125f * (q2r0 + k2p.y - 2.f * e[nt][1]));
            float e10 = __expf(-0.125f * (q2r1 + k2p.x - 2.f * e[nt][2]));
            float e11 = __expf(-0.125f * (q2r1 + k2p.y - 2.f * e[nt][3]));
            e[nt][0] = e00; e[nt][1] = e01; e[nt][2] = e10; e[nt][3] = e11;
            rs0 += e00 + e01;
            rs1 += e10 + e11;
            if (do_attn) {
                size_t a0i = (size_t)(row0 + wm * 16 + g) * SEQ + kb * KT + cg;
                *(float2*)&attn[a0i]             = make_float2(e00, e01);
                *(float2*)&attn[a0i + 8 * SEQ]   = make_float2(e10, e11);
            }
        }

        #pragma unroll
        for (int kk = 0; kk < 8; kk++) {
            float v0 = __shfl_sync(0xffffffffu, e[kk][0], srcA);
            float v1 = __shfl_sync(0xffffffffu, e[kk][1], srcA);
            float v2 = __shfl_sync(0xffffffffu, e[kk][2], srcA);
            float v3 = __shfl_sync(0xffffffffu, e[kk][3], srcA);
            float w0 = __shfl_sync(0xffffffffu, e[kk][0], srcB);
            float w1 = __shfl_sync(0xffffffffu, e[kk][1], srcB);
            float w2 = __shfl_sync(0xffffffffu, e[kk][2], srcB);
            float w3 = __shfl_sync(0xffffffffu, e[kk][3], srcB);
            float a0 = odd ? v1 : v0, a1 = odd ? v3 : v2;
            float a2 = odd ? w1 : w0, a3 = odd ? w3 : w2;
            float ab0 = tf32_rna(a0), ab1 = tf32_rna(a1), ab2 = tf32_rna(a2), ab3 = tf32_rna(a3);
            float as0 = a0 - ab0, as1 = a1 - ab1, as2 = a2 - ab2, as3 = a3 - ab3;
            #pragma unroll
            for (int nt = 0; nt < 8; nt++) {
                int br = (wn * 64 + kk * 8 + tig) * 72 + nt * 8 + g;
                float b0 = Vs[br], b1 = Vs[br + 4 * 72];
                mma3_tf32(cacc[nt], ab0, ab1, ab2, ab3, as0, as1, as2, as3, b0, b1);
            }
        }
        __syncthreads();
    }

    rs0 += __shfl_xor_sync(0xffffffffu, rs0, 1);
    rs0 += __shfl_xor_sync(0xffffffffu, rs0, 2);
    rs1 += __shfl_xor_sync(0xffffffffu, rs1, 1);
    rs1 += __shfl_xor_sync(0xffffffffu, rs1, 2);
    if (tig == 0) {
        red[wn * 64 + wm * 16 + g]     = rs0;
        red[wn * 64 + wm * 16 + g + 8] = rs1;
    }
    __syncthreads();
    if (tid < 64) rinv[tid] = 1.0f / (red[tid] + red[64 + tid]);
    __syncthreads();

    if (wn == 0) {
        #pragma unroll
        for (int nt = 0; nt < 8; nt++) {
            int c = nt * 8 + 2 * tig;
            *(float2*)&ctmp[(wm * 16 + g) * 68 + c]       = make_float2(cacc[nt][0], cacc[nt][1]);
            *(float2*)&ctmp[(wm * 16 + g + 8) * 68 + c]   = make_float2(cacc[nt][2], cacc[nt][3]);
        }
    }
    __syncthreads();
    if (wn == 1) {
        float ri0 = rinv[wm * 16 + g];
        float ri1 = rinv[wm * 16 + g + 8];
        int r0_ = row0 + wm * 16 + g;
        #pragma unroll
        for (int nt = 0; nt < 8; nt++) {
            int c = nt * 8 + 2 * tig;
            float2 p0 = *(float2*)&ctmp[(wm * 16 + g) * 68 + c];
            float2 p1 = *(float2*)&ctmp[(wm * 16 + g + 8) * 68 + c];
            *(float2*)&g_ctx[(size_t)r0_ * HDIM + c] =
                make_float2((cacc[nt][0] + p0.x) * ri0, (cacc[nt][1] + p0.y) * ri0);
            *(float2*)&g_ctx[(size_t)(r0_ + 8) * HDIM + c] =
                make_float2((cacc[nt][2] + p1.x) * ri1, (cacc[nt][3] + p1.y) * ri1);
        }
    }

    if (do_attn) {
        for (int kb = 0; kb < NKB; kb++) {
            #pragma unroll
            for (int it = 0; it < 8; it++) {
                int f = it * 256 + tid;
                int r = f >> 5, c4 = (f & 31) * 4;
                float ri = rinv[r];
                float* p = &attn[(size_t)(row0 + r) * SEQ + kb * KT + c4];
                float4 v4 = *(float4*)p;
                v4.x *= ri; v4.y *= ri; v4.z *= ri; v4.w *= ri;
                *(float4*)p = v4;
            }
        }
    }
}

// ============== out = ctx @ Wo + bo ==============
__global__ __launch_bounds__(256) void k_out(
    const float* __restrict__ Wo, const float* __restrict__ bo, float* __restrict__ out)
{
    __shared__ float cs[4][64];
    int tid = threadIdx.x;
    int r = tid >> 6, h = tid & 63;
    int row = blockIdx.x * 4 + r;
    cs[r][h] = g_ctx[(size_t)row * HDIM + h];
    __syncthreads();
    float o = bo[h];
    #pragma unroll 16
    for (int hp = 0; hp < HDIM; hp++) o += cs[r][hp] * Wo[hp * HDIM + h];
    out[(size_t)row * HDIM + h] = o;
}

// =========================== launch ===========================
extern "C" void kernel_launch(void* const* d_in, const int* in_sizes, int n_in,
                              void* d_out, int out_size)
{
    const float* qs = (const float*)d_in[0];
    const float* ks = (const float*)d_in[1];
    const float* vs = (const float*)d_in[2];
    const float* Wq = (const float*)d_in[3];
    const float* bq = (const float*)d_in[4];
    const float* Wk = (const float*)d_in[5];
    const float* bk = (const float*)d_in[6];
    const float* Wv = (const float*)d_in[7];
    const float* bv = (const float*)d_in[8];
    const float* Wo = (const float*)d_in[9];
    const float* bo = (const float*)d_in[10];

    const int OUTN = ROWS * HDIM;        // 524288
    const int ATTN = ROWS * SEQ;         // 16777216

    float* souts = nullptr;
    cudaGetSymbolAddress((void**)&souts, g_outs);

    float* outp; float* attnp;
    if (out_size >= OUTN + ATTN)      { outp = (float*)d_out; attnp = (float*)d_out + OUTN; }
    else if (out_size == ATTN)        { outp = souts;         attnp = (float*)d_out; }
    else                              { outp = (float*)d_out; attnp = nullptr; }

    cudaFuncSetAttribute(k_proj,  cudaFuncAttributeMaxDynamicSharedMemorySize, PJ_BYTES);
    cudaFuncSetAttribute(k_attn2, cudaFuncAttributeMaxDynamicSharedMemorySize, SMEM_BYTES);

    k_proj<<<dim3(ROWS / 64, 3), 256, PJ_BYTES>>>(qs, ks, vs, Wq, bq, Wk, bk, Wv, bv);
    k_attn2<<<ROWS / TQ, 256, SMEM_BYTES>>>(attnp ? attnp : (float*)d_out,
                                            attnp != nullptr ? 1 : 0);
    k_out<<<ROWS / 4, 256>>>(Wo, bo, outp);
}

// round 11
// speedup vs baseline: 1.3982x; 1.0914x over previous
#include <cuda_runtime.h>
#include <cstdint>

#define BATCH 4
#define SEQ   2048
#define DIN   128
#define HDIM  64
#define ROWS  (BATCH*SEQ)        // 8192
#define TQ    64
#define KT    128
#define NKB   (SEQ/KT)           // 16

// ---- device scratch ----
__device__ float g_q [ROWS*HDIM];
__device__ float g_k [ROWS*HDIM];
__device__ float g_v [ROWS*HDIM];
__device__ float g_q2[ROWS];
__device__ float g_k2[ROWS];
__device__ float g_ctx[ROWS*HDIM];
__device__ float g_outs[ROWS*HDIM];

// ================= cp.async helpers =================
__device__ __forceinline__ void cpa16(void* dst_smem, const void* src) {
    unsigned d = (unsigned)__cvta_generic_to_shared(dst_smem);
    asm volatile("cp.async.cg.shared.global [%0], [%1], 16;\n" :: "r"(d), "l"(src));
}
#define CP_COMMIT() asm volatile("cp.async.commit_group;\n")
#define CP_WAIT(N)  asm volatile("cp.async.wait_group %0;\n" :: "n"(N))

// ================= tf32 mma + split =================
__device__ __forceinline__ float tf32_rna(float x) {
    uint32_t r; asm("cvt.rna.tf32.f32 %0, %1;\n" : "=r"(r) : "f"(x));
    return __uint_as_float(r);
}
__device__ __forceinline__ void mma_tf32(float& d0, float& d1, float& d2, float& d3,
                                         float a0, float a1, float a2, float a3,
                                         float b0, float b1)
{
    asm volatile(
        "mma.sync.aligned.m16n8k8.row.col.f32.tf32.tf32.f32 "
        "{%0,%1,%2,%3}, {%4,%5,%6,%7}, {%8,%9}, {%0,%1,%2,%3};\n"
        : "+f"(d0), "+f"(d1), "+f"(d2), "+f"(d3)
        : "r"(__float_as_uint(a0)), "r"(__float_as_uint(a1)),
          "r"(__float_as_uint(a2)), "r"(__float_as_uint(a3)),
          "r"(__float_as_uint(b0)), "r"(__float_as_uint(b1)));
}
__device__ __forceinline__ void mma3_tf32(float* acc,
    float ab0, float ab1, float ab2, float ab3,
    float as0, float as1, float as2, float as3,
    float b0, float b1)
{
    float bb0 = tf32_rna(b0), bb1 = tf32_rna(b1);
    float bs0 = b0 - bb0,     bs1 = b1 - bb1;
    mma_tf32(acc[0], acc[1], acc[2], acc[3], ab0, ab1, ab2, ab3, bb0, bb1);
    mma_tf32(acc[0], acc[1], acc[2], acc[3], ab0, ab1, ab2, ab3, bs0, bs1);
    mma_tf32(acc[0], acc[1], acc[2], acc[3], as0, as1, as2, as3, bb0, bb1);
}

// ================= projections via tensor cores (3xTF32) =================
#define PJ_WS (64*132)
#define PJ_SQ (PJ_WS + 128*72)
#define PJ_BYTES ((PJ_SQ + 128) * 4)

__global__ __launch_bounds__(256) void k_proj(
    const float* __restrict__ qs, const float* __restrict__ ks, const float* __restrict__ vs,
    const float* __restrict__ Wq, const float* __restrict__ bq,
    const float* __restrict__ Wk, const float* __restrict__ bk,
    const float* __restrict__ Wv, const float* __restrict__ bv)
{
    extern __shared__ float psm[];
    float* Xs  = psm;
    float* Ws  = psm + PJ_WS;
    float* sqp = psm + PJ_SQ;

    const float* X; const float* W; const float* bias; float* Y; float* sq;
    int mode = blockIdx.y;
    switch (mode) {
        case 0:  X = qs; W = Wq; bias = bq; Y = g_q; sq = g_q2; break;
        case 1:  X = ks; W = Wk; bias = bk; Y = g_k; sq = g_k2; break;
        default: X = vs; W = Wv; bias = bv; Y = g_v; sq = nullptr; break;
    }
    const int tid  = threadIdx.x;
    const int lane = tid & 31;
    const int wid  = tid >> 5;
    const int g    = lane >> 2;
    const int tig  = lane & 3;
    const int wm   = wid & 3;
    const int wn   = wid >> 2;
    const int row0 = blockIdx.x * 64;

    #pragma unroll
    for (int it = 0; it < 8; it++) {
        int op = it * 256 + tid;
        int r = op >> 5, c = (op & 31) * 4;
        cpa16(&Xs[r * 132 + c], &X[(size_t)(row0 + r) * DIN + c]);
    }
    #pragma unroll
    for (int it = 0; it < 8; it++) {
        int op = it * 256 + tid;
        int r = op >> 4, c = (op & 15) * 4;
        cpa16(&Ws[r * 72 + c], &W[(size_t)r * HDIM + c]);
    }
    CP_COMMIT(); CP_WAIT(0);
    __syncthreads();

    float acc[4][4];
    #pragma unroll
    for (int i = 0; i < 4; i++)
        #pragma unroll
        for (int j = 0; j < 4; j++) acc[i][j] = 0.f;

    #pragma unroll
    for (int kk = 0; kk < 16; kk++) {
        int ar = (wm * 16 + g) * 132 + kk * 8 + tig;
        float a0 = Xs[ar], a1 = Xs[ar + 8 * 132], a2 = Xs[ar + 4], a3 = Xs[ar + 8 * 132 + 4];
        float ab0 = tf32_rna(a0), ab1 = tf32_rna(a1), ab2 = tf32_rna(a2), ab3 = tf32_rna(a3);
        float as0 = a0 - ab0, as1 = a1 - ab1, as2 = a2 - ab2, as3 = a3 - ab3;
        #pragma unroll
        for (int nt = 0; nt < 4; nt++) {
            int br = (kk * 8 + tig) * 72 + wn * 32 + nt * 8 + g;
            float b0 = Ws[br], b1 = Ws[br + 4 * 72];
            mma3_tf32(acc[nt], ab0, ab1, ab2, ab3, as0, as1, as2, as3, b0, b1);
        }
    }

    float p0 = 0.f, p1 = 0.f;
    #pragma unroll
    for (int nt = 0; nt < 4; nt++) {
        int c = wn * 32 + nt * 8 + 2 * tig;
        float2 bb = *(const float2*)&bias[c];
        float y00 = acc[nt][0] + bb.x, y01 = acc[nt][1] + bb.y;
        float y10 = acc[nt][2] + bb.x, y11 = acc[nt][3] + bb.y;
        p0 += y00 * y00 + y01 * y01;
        p1 += y10 * y10 + y11 * y11;
        int r = row0 + wm * 16 + g;
        *(float2*)&Y[(size_t)r * HDIM + c]       = make_float2(y00, y01);
        *(float2*)&Y[(size_t)(r + 8) * HDIM + c] = make_float2(y10, y11);
    }
    if (sq) {
        p0 += __shfl_xor_sync(0xffffffffu, p0, 1);
        p0 += __shfl_xor_sync(0xffffffffu, p0, 2);
        p1 += __shfl_xor_sync(0xffffffffu, p1, 1);
        p1 += __shfl_xor_sync(0xffffffffu, p1, 2);
        if (tig == 0) {
            sqp[wn * 64 + wm * 16 + g]     = p0;
            sqp[wn * 64 + wm * 16 + g + 8] = p1;
        }
        __syncthreads();
        if (tid < 64) sq[row0 + tid] = sqp[tid] + sqp[64 + tid];
    }
}

// ======== fused attention: 512 threads, 16 warps (4m x 4n), TQ=64 over all k ========
#define OFF_QS   0
#define OFF_KS0  (OFF_QS  + 64*68)
#define OFF_KS1  (OFF_KS0 + 128*76)
#define OFF_VS0  (OFF_KS1 + 128*76)
#define OFF_VS1  (OFF_VS0 + 128*72)
#define OFF_K20  (OFF_VS1 + 128*72)
#define OFF_K21  (OFF_K20 + 128)
#define OFF_RED  (OFF_K21 + 128)
#define OFF_RINV (OFF_RED + 256)
#define SMEM_FLOATS (OFF_RINV + 64)
#define SMEM_BYTES  (SMEM_FLOATS * 4)   // 171264
// ctmp [4][64][68] aliases the dead K/V buffers after the k-loop (17408 floats < KS region)
#define OFF_CT   OFF_KS0

__global__ __launch_bounds__(512, 1) void k_attn2(float* __restrict__ attn, int do_attn)
{
    extern __shared__ float sm[];
    float* Qs = sm + OFF_QS;                          // [64][68]
    float* KsB[2] = { sm + OFF_KS0, sm + OFF_KS1 };   // [s(128)][h] stride 76
    float* VsB[2] = { sm + OFF_VS0, sm + OFF_VS1 };   // [s(128)][h] stride 72
    float* k2B[2] = { sm + OFF_K20, sm + OFF_K21 };
    float* red  = sm + OFF_RED;                       // [4][64]
    float* rinv = sm + OFF_RINV;                      // [64]
    float* ctmp = sm + OFF_CT;                        // [4][64][68] (aliased)

    const int tid  = threadIdx.x;
    const int lane = tid & 31;
    const int wid  = tid >> 5;       // 0..15
    const int g    = lane >> 2;
    const int tig  = lane & 3;
    const int wm   = wid & 3;        // 4 m-tiles of 16 rows
    const int wn   = wid >> 2;       // 4 n/k quarters

    const int row0 = blockIdx.x * TQ;
    const int b    = row0 >> 11;
    const float* k_base  = g_k  + (size_t)b * SEQ * HDIM;
    const float* v_base  = g_v  + (size_t)b * SEQ * HDIM;
    const float* k2_base = g_k2 + b * SEQ;

    // ---- prologue: stage Q + tile 0 ----
    #pragma unroll
    for (int it = 0; it < 2; it++) {                  // Q: 1024 x 16B
        int op = it * 512 + tid;
        int r = op >> 4, c = (op & 15) * 4;
        cpa16(&Qs[r * 68 + c], &g_q[(size_t)(row0 + r) * HDIM + c]);
    }
    #pragma unroll
    for (int it = 0; it < 4; it++) {                  // K,V: 2048 x 16B each
        int op = it * 512 + tid;
        int r = op >> 4, c = (op & 15) * 4;
        cpa16(&KsB[0][r * 76 + c], k_base + (size_t)r * HDIM + c);
        cpa16(&VsB[0][r * 72 + c], v_base + (size_t)r * HDIM + c);
    }
    if (tid < 32) cpa16(&k2B[0][tid * 4], k2_base + tid * 4);
    CP_COMMIT();

    float q2r0 = g_q2[row0 + wm * 16 + g];
    float q2r1 = g_q2[row0 + wm * 16 + g + 8];

    float rs0 = 0.f, rs1 = 0.f;
    float cacc[8][4];
    #pragma unroll
    for (int i = 0; i < 8; i++)
        #pragma unroll
        for (int j = 0; j < 4; j++) cacc[i][j] = 0.f;

    const int srcA = (lane & ~3) | (tig >> 1);
    const int srcB = srcA + 2;
    const bool odd = (tig & 1);

    for (int kb = 0; kb < NKB; kb++) {
        const int bf = kb & 1;
        if (kb + 1 < NKB) {
            const int nb = (kb + 1) & 1;
            const float* kn = k_base + (size_t)(kb + 1) * KT * HDIM;
            const float* vn = v_base + (size_t)(kb + 1) * KT * HDIM;
            #pragma unroll
            for (int it = 0; it < 4; it++) {
                int op = it * 512 + tid;
                int r = op >> 4, c = (op & 15) * 4;
                cpa16(&KsB[nb][r * 76 + c], kn + (size_t)r * HDIM + c);
                cpa16(&VsB[nb][r * 72 + c], vn + (size_t)r * HDIM + c);
            }
            if (tid < 32) cpa16(&k2B[nb][tid * 4], k2_base + (kb + 1) * KT + tid * 4);
            CP_COMMIT();
            CP_WAIT(1);
        } else {
            CP_WAIT(0);
        }
        __syncthreads();

        const float* Ks  = KsB[bf];
        const float* Vs  = VsB[bf];
        const float* k2s = k2B[bf];

        // ---- scores (1x tf32): warp tile 16 x 32 (cols wn*32..+32) ----
        float e[4][4];
        #pragma unroll
        for (int nt = 0; nt < 4; nt++) {
            e[nt][0] = 0.f; e[nt][1] = 0.f; e[nt][2] = 0.f; e[nt][3] = 0.f;
        }
        #pragma unroll
        for (int kk = 0; kk < 8; kk++) {
            int ar = (wm * 16 + g) * 68 + kk * 8 + tig;
            float a0 = Qs[ar];
            float a1 = Qs[ar + 8 * 68];
            float a2 = Qs[ar + 4];
            float a3 = Qs[ar + 8 * 68 + 4];
            #pragma unroll
            for (int nt = 0; nt < 4; nt++) {
                int br = (wn * 32 + nt * 8 + g) * 76 + kk * 8 + tig;
                float b0 = Ks[br], b1 = Ks[br + 4];
                mma_tf32(e[nt][0], e[nt][1], e[nt][2], e[nt][3], a0, a1, a2, a3, b0, b1);
            }
        }

        // ---- exp in place + rowsum partial + attn store ----
        #pragma unroll
        for (int nt = 0; nt < 4; nt++) {
            int cg = wn * 32 + nt * 8 + 2 * tig;
            float2 k2p = *(const float2*)&k2s[cg];
            float e00 = __expf(-0.125f * (q2r0 + k2p.x - 2.f * e[nt][0]));
            float e01 = __expf(-0.125f * (q2r0 + k2p.y - 2.f * e[nt][1]));
            float e10 = __expf(-0.125f * (q2r1 + k2p.x - 2.f * e[nt][2]));
            float e11 = __expf(-0.125f * (q2r1 + k2p.y - 2.f * e[nt][3]));
            e[nt][0] = e00; e[nt][1] = e01; e[nt][2] = e10; e[nt][3] = e11;
            rs0 += e00 + e01;
            rs1 += e10 + e11;
            if (do_attn) {
                size_t a0i = (size_t)(row0 + wm * 16 + g) * SEQ + kb * KT + cg;
                *(float2*)&attn[a0i]           = make_float2(e00, e01);
                *(float2*)&attn[a0i + 8 * SEQ] = make_float2(e10, e11);
            }
        }

        // ---- ctx (3x tf32): warp consumes its own 32 k-rows (4 chunks), full 64 h ----
        #pragma unroll
        for (int c = 0; c < 4; c++) {
            float v0 = __shfl_sync(0xffffffffu, e[c][0], srcA);
            float v1 = __shfl_sync(0xffffffffu, e[c][1], srcA);
            float v2 = __shfl_sync(0xffffffffu, e[c][2], srcA);
            float v3 = __shfl_sync(0xffffffffu, e[c][3], srcA);
            float w0 = __shfl_sync(0xffffffffu, e[c][0], srcB);
            float w1 = __shfl_sync(0xffffffffu, e[c][1], srcB);
            float w2 = __shfl_sync(0xffffffffu, e[c][2], srcB);
            float w3 = __shfl_sync(0xffffffffu, e[c][3], srcB);
            float a0 = odd ? v1 : v0, a1 = odd ? v3 : v2;
            float a2 = odd ? w1 : w0, a3 = odd ? w3 : w2;
            float ab0 = tf32_rna(a0), ab1 = tf32_rna(a1), ab2 = tf32_rna(a2), ab3 = tf32_rna(a3);
            float as0 = a0 - ab0, as1 = a1 - ab1, as2 = a2 - ab2, as3 = a3 - ab3;
            #pragma unroll
            for (int nt = 0; nt < 8; nt++) {
                int br = (wn * 32 + c * 8 + tig) * 72 + nt * 8 + g;
                float b0 = Vs[br], b1 = Vs[br + 4 * 72];
                mma3_tf32(cacc[nt], ab0, ab1, ab2, ab3, as0, as1, as2, as3, b0, b1);
            }
        }
        __syncthreads();
    }

    // ---- rowsum reduce (4 wn quarters per row) -> rinv ----
    rs0 += __shfl_xor_sync(0xffffffffu, rs0, 1);
    rs0 += __shfl_xor_sync(0xffffffffu, rs0, 2);
    rs1 += __shfl_xor_sync(0xffffffffu, rs1, 1);
    rs1 += __shfl_xor_sync(0xffffffffu, rs1, 2);
    if (tig == 0) {
        red[wn * 64 + wm * 16 + g]     = rs0;
        red[wn * 64 + wm * 16 + g + 8] = rs1;
    }
    __syncthreads();
    if (tid < 64)
        rinv[tid] = 1.0f / (red[tid] + red[64 + tid] + red[128 + tid] + red[192 + tid]);
    __syncthreads();   // also: all reads of K/V buffers complete before ctmp aliasing

    // ---- combine ctx quarters via ctmp (aliased over dead K/V smem) ----
    #pragma unroll
    for (int nt = 0; nt < 8; nt++) {
        int c = nt * 8 + 2 * tig;
        *(float2*)&ctmp[wn * 64 * 68 + (wm * 16 + g) * 68 + c]     = make_float2(cacc[nt][0], cacc[nt][1]);
        *(float2*)&ctmp[wn * 64 * 68 + (wm * 16 + g + 8) * 68 + c] = make_float2(cacc[nt][2], cacc[nt][3]);
    }
    __syncthreads();
    #pragma unroll
    for (int it = 0; it < 8; it++) {
        int idx = it * 512 + tid;         // 0..4095
        int r = idx >> 6, c = idx & 63;
        float s = ctmp[r * 68 + c] + ctmp[64 * 68 + r * 68 + c]
                + ctmp[2 * 64 * 68 + r * 68 + c] + ctmp[3 * 64 * 68 + r * 68 + c];
        g_ctx[(size_t)(row0 + r) * HDIM + c] = s * rinv[r];
    }

    // ---- normalize attn in place ----
    if (do_attn) {
        for (int kb = 0; kb < NKB; kb++) {
            #pragma unroll
            for (int it = 0; it < 4; it++) {
                int f = it * 512 + tid;
                int r = f >> 5, c4 = (f & 31) * 4;
                float ri = rinv[r];
                float* p = &attn[(size_t)(row0 + r) * SEQ + kb * KT + c4];
                float4 v4 = *(float4*)p;
                v4.x *= ri; v4.y *= ri; v4.z *= ri; v4.w *= ri;
                *(float4*)p = v4;
            }
        }
    }
}

// ============== out = ctx @ Wo + bo ==============
__global__ __launch_bounds__(256) void k_out(
    const float* __restrict__ Wo, const float* __restrict__ bo, float* __restrict__ out)
{
    __shared__ float cs[4][64];
    int tid = threadIdx.x;
    int r = tid >> 6, h = tid & 63;
    int row = blockIdx.x * 4 + r;
    cs[r][h] = g_ctx[(size_t)row * HDIM + h];
    __syncthreads();
    float o = bo[h];
    #pragma unroll 16
    for (int hp = 0; hp < HDIM; hp++) o += cs[r][hp] * Wo[hp * HDIM + h];
    out[(size_t)row * HDIM + h] = o;
}

// =========================== launch ===========================
extern "C" void kernel_launch(void* const* d_in, const int* in_sizes, int n_in,
                              void* d_out, int out_size)
{
    const float* qs = (const float*)d_in[0];
    const float* ks = (const float*)d_in[1];
    const float* vs = (const float*)d_in[2];
    const float* Wq = (const float*)d_in[3];
    const float* bq = (const float*)d_in[4];
    const float* Wk = (const float*)d_in[5];
    const float* bk = (const float*)d_in[6];
    const float* Wv = (const float*)d_in[7];
    const float* bv = (const float*)d_in[8];
    const float* Wo = (const float*)d_in[9];
    const float* bo = (const float*)d_in[10];

    const int OUTN = ROWS * HDIM;        // 524288
    const int ATTN = ROWS * SEQ;         // 16777216

    float* souts = nullptr;
    cudaGetSymbolAddress((void**)&souts, g_outs);

    float* outp; float* attnp;
    if (out_size >= OUTN + ATTN)      { outp = (float*)d_out; attnp = (float*)d_out + OUTN; }
    else if (out_size == ATTN)        { outp = souts;         attnp = (float*)d_out; }
    else                              { outp = (float*)d_out; attnp = nullptr; }

    cudaFuncSetAttribute(k_proj,  cudaFuncAttributeMaxDynamicSharedMemorySize, PJ_BYTES);
    cudaFuncSetAttribute(k_attn2, cudaFuncAttributeMaxDynamicSharedMemorySize, SMEM_BYTES);

    k_proj<<<dim3(ROWS / 64, 3), 256, PJ_BYTES>>>(qs, ks, vs, Wq, bq, Wk, bk, Wv, bv);
    k_attn2<<<ROWS / TQ, 512, SMEM_BYTES>>>(attnp ? attnp : (float*)d_out,
                                            attnp != nullptr ? 1 : 0);
    k_out<<<ROWS / 4, 256>>>(Wo, bo, outp);
}

// round 12
// speedup vs baseline: 1.5499x; 1.1084x over previous
#include <cuda_runtime.h>
#include <cuda_bf16.h>
#include <cstdint>

#define BATCH 4
#define SEQ   2048
#define DIN   128
#define HDIM  64
#define ROWS  (BATCH*SEQ)        // 8192
#define TQ    64
#define KT    128
#define NKB   (SEQ/KT)           // 16

// ---- device scratch ----
__device__ float g_q [ROWS*HDIM];
__device__ float g_k [ROWS*HDIM];
__device__ __nv_bfloat16 g_vth[BATCH*HDIM*SEQ];   // V^T hi, [b][h][s]
__device__ __nv_bfloat16 g_vtl[BATCH*HDIM*SEQ];   // V^T lo
__device__ float g_q2[ROWS];
__device__ float g_k2[ROWS];
__device__ float g_ctx[ROWS*HDIM];
__device__ float g_outs[ROWS*HDIM];

// ================= cp.async helpers =================
__device__ __forceinline__ void cpa16(void* dst_smem, const void* src) {
    unsigned d = (unsigned)__cvta_generic_to_shared(dst_smem);
    asm volatile("cp.async.cg.shared.global [%0], [%1], 16;\n" :: "r"(d), "l"(src));
}
#define CP_COMMIT() asm volatile("cp.async.commit_group;\n")
#define CP_WAIT(N)  asm volatile("cp.async.wait_group %0;\n" :: "n"(N))

// ================= mma wrappers =================
__device__ __forceinline__ float tf32_rna(float x) {
    uint32_t r; asm("cvt.rna.tf32.f32 %0, %1;\n" : "=r"(r) : "f"(x));
    return __uint_as_float(r);
}
__device__ __forceinline__ void mma_tf32(float& d0, float& d1, float& d2, float& d3,
                                         float a0, float a1, float a2, float a3,
                                         float b0, float b1)
{
    asm volatile(
        "mma.sync.aligned.m16n8k8.row.col.f32.tf32.tf32.f32 "
        "{%0,%1,%2,%3}, {%4,%5,%6,%7}, {%8,%9}, {%0,%1,%2,%3};\n"
        : "+f"(d0), "+f"(d1), "+f"(d2), "+f"(d3)
        : "r"(__float_as_uint(a0)), "r"(__float_as_uint(a1)),
          "r"(__float_as_uint(a2)), "r"(__float_as_uint(a3)),
          "r"(__float_as_uint(b0)), "r"(__float_as_uint(b1)));
}
__device__ __forceinline__ void mma3_tf32(float* acc,
    float ab0, float ab1, float ab2, float ab3,
    float as0, float as1, float as2, float as3,
    float b0, float b1)
{
    float bb0 = tf32_rna(b0), bb1 = tf32_rna(b1);
    float bs0 = b0 - bb0,     bs1 = b1 - bb1;
    mma_tf32(acc[0], acc[1], acc[2], acc[3], ab0, ab1, ab2, ab3, bb0, bb1);
    mma_tf32(acc[0], acc[1], acc[2], acc[3], ab0, ab1, ab2, ab3, bs0, bs1);
    mma_tf32(acc[0], acc[1], acc[2], acc[3], as0, as1, as2, as3, bb0, bb1);
}
__device__ __forceinline__ void mma_bf16(float* acc,
    uint32_t a0, uint32_t a1, uint32_t a2, uint32_t a3, uint32_t b0, uint32_t b1)
{
    asm volatile(
        "mma.sync.aligned.m16n8k16.row.col.f32.bf16.bf16.f32 "
        "{%0,%1,%2,%3}, {%4,%5,%6,%7}, {%8,%9}, {%0,%1,%2,%3};\n"
        : "+f"(acc[0]), "+f"(acc[1]), "+f"(acc[2]), "+f"(acc[3])
        : "r"(a0), "r"(a1), "r"(a2), "r"(a3), "r"(b0), "r"(b1));
}
// pack two f32 -> bf16x2 ({lo: x0, hi: x1}) and produce residual pack
__device__ __forceinline__ uint32_t pack_bf(float x0, float x1) {
    uint32_t r; asm("cvt.rn.bf16x2.f32 %0, %1, %2;\n" : "=r"(r) : "f"(x1), "f"(x0));
    return r;
}
__device__ __forceinline__ void split_bf(float x0, float x1, uint32_t& hi, uint32_t& lo) {
    hi = pack_bf(x0, x1);
    float h0 = __uint_as_float(hi << 16);
    float h1 = __uint_as_float(hi & 0xffff0000u);
    lo = pack_bf(x0 - h0, x1 - h1);
}

// ---- dummy kernels to shift the ncu -s window onto k_attn2 ----
__global__ void k_nop1() {}
__global__ void k_nop2() {}

// ================= projections via tensor cores (3xTF32) =================
#define PJ_WS (64*132)
#define PJ_SQ (PJ_WS + 128*72)
#define PJ_BYTES ((PJ_SQ + 128) * 4)

__global__ __launch_bounds__(256) void k_proj(
    const float* __restrict__ qs, const float* __restrict__ ks, const float* __restrict__ vs,
    const float* __restrict__ Wq, const float* __restrict__ bq,
    const float* __restrict__ Wk, const float* __restrict__ bk,
    const float* __restrict__ Wv, const float* __restrict__ bv)
{
    extern __shared__ float psm[];
    float* Xs  = psm;
    float* Ws  = psm + PJ_WS;
    float* sqp = psm + PJ_SQ;

    const float* X; const float* W; const float* bias; float* Y; float* sq;
    int mode = blockIdx.y;
    switch (mode) {
        case 0:  X = qs; W = Wq; bias = bq; Y = g_q; sq = g_q2; break;
        case 1:  X = ks; W = Wk; bias = bk; Y = g_k; sq = g_k2; break;
        default: X = vs; W = Wv; bias = bv; Y = nullptr; sq = nullptr; break;
    }
    const int tid  = threadIdx.x;
    const int lane = tid & 31;
    const int wid  = tid >> 5;
    const int g    = lane >> 2;
    const int tig  = lane & 3;
    const int wm   = wid & 3;
    const int wn   = wid >> 2;
    const int row0 = blockIdx.x * 64;

    #pragma unroll
    for (int it = 0; it < 8; it++) {
        int op = it * 256 + tid;
        int r = op >> 5, c = (op & 31) * 4;
        cpa16(&Xs[r * 132 + c], &X[(size_t)(row0 + r) * DIN + c]);
    }
    #pragma unroll
    for (int it = 0; it < 8; it++) {
        int op = it * 256 + tid;
        int r = op >> 4, c = (op & 15) * 4;
        cpa16(&Ws[r * 72 + c], &W[(size_t)r * HDIM + c]);
    }
    CP_COMMIT(); CP_WAIT(0);
    __syncthreads();

    float acc[4][4];
    #pragma unroll
    for (int i = 0; i < 4; i++)
        #pragma unroll
        for (int j = 0; j < 4; j++) acc[i][j] = 0.f;

    #pragma unroll
    for (int kk = 0; kk < 16; kk++) {
        int ar = (wm * 16 + g) * 132 + kk * 8 + tig;
        float a0 = Xs[ar], a1 = Xs[ar + 8 * 132], a2 = Xs[ar + 4], a3 = Xs[ar + 8 * 132 + 4];
        float ab0 = tf32_rna(a0), ab1 = tf32_rna(a1), ab2 = tf32_rna(a2), ab3 = tf32_rna(a3);
        float as0 = a0 - ab0, as1 = a1 - ab1, as2 = a2 - ab2, as3 = a3 - ab3;
        #pragma unroll
        for (int nt = 0; nt < 4; nt++) {
            int br = (kk * 8 + tig) * 72 + wn * 32 + nt * 8 + g;
            float b0 = Ws[br], b1 = Ws[br + 4 * 72];
            mma3_tf32(acc[nt], ab0, ab1, ab2, ab3, as0, as1, as2, as3, b0, b1);
        }
    }

    const int rr = row0 + wm * 16 + g;
    float p0 = 0.f, p1 = 0.f;
    if (mode == 2) {
        int bb_ = rr >> 11;
        int s   = rr & (SEQ - 1);
        #pragma unroll
        for (int nt = 0; nt < 4; nt++) {
            int c = wn * 32 + nt * 8 + 2 * tig;
            float2 bbv = *(const float2*)&bias[c];
            float y[4] = { acc[nt][0] + bbv.x, acc[nt][1] + bbv.y,
                           acc[nt][2] + bbv.x, acc[nt][3] + bbv.y };
            size_t base0 = ((size_t)bb_ * HDIM + c) * SEQ;
            size_t base1 = base0 + SEQ;
            // (row rr, col c), (rr, c+1), (rr+8, c), (rr+8, c+1)
            size_t idx[4] = { base0 + s, base1 + s, base0 + s + 8, base1 + s + 8 };
            #pragma unroll
            for (int j = 0; j < 4; j++) {
                __nv_bfloat16 h = __float2bfloat16_rn(y[j]);
                float hf = __uint_as_float(((uint32_t)__bfloat16_as_ushort(h)) << 16);
                g_vth[idx[j]] = h;
                g_vtl[idx[j]] = __float2bfloat16_rn(y[j] - hf);
            }
        }
    } else {
        #pragma unroll
        for (int nt = 0; nt < 4; nt++) {
            int c = wn * 32 + nt * 8 + 2 * tig;
            float2 bbv = *(const float2*)&bias[c];
            float y00 = acc[nt][0] + bbv.x, y01 = acc[nt][1] + bbv.y;
            float y10 = acc[nt][2] + bbv.x, y11 = acc[nt][3] + bbv.y;
            p0 += y00 * y00 + y01 * y01;
            p1 += y10 * y10 + y11 * y11;
            *(float2*)&Y[(size_t)rr * HDIM + c]       = make_float2(y00, y01);
            *(float2*)&Y[(size_t)(rr + 8) * HDIM + c] = make_float2(y10, y11);
        }
        p0 += __shfl_xor_sync(0xffffffffu, p0, 1);
        p0 += __shfl_xor_sync(0xffffffffu, p0, 2);
        p1 += __shfl_xor_sync(0xffffffffu, p1, 1);
        p1 += __shfl_xor_sync(0xffffffffu, p1, 2);
        if (tig == 0) {
            sqp[wn * 64 + wm * 16 + g]     = p0;
            sqp[wn * 64 + wm * 16 + g + 8] = p1;
        }
        __syncthreads();
        if (tid < 64) sq[row0 + tid] = sqp[tid] + sqp[64 + tid];
    }
}

// ======== fused attention: 512 threads, 16 warps (4m x 4n), TQ=64 over all k ========
// byte offsets
#define OFF_QS   0                         // f32 [64][68]  = 17408 B
#define OFF_KS0  17408                     // f32 [128][76] = 38912 B
#define OFF_KS1  (OFF_KS0 + 38912)
#define OFF_VH0  (OFF_KS1 + 38912)         // bf16 [64][136] = 17408 B
#define OFF_VH1  (OFF_VH0 + 17408)
#define OFF_VL0  (OFF_VH1 + 17408)
#define OFF_VL1  (OFF_VL0 + 17408)
#define OFF_K20  (OFF_VL1 + 17408)         // f32 [128]
#define OFF_K21  (OFF_K20 + 512)
#define OFF_RED  (OFF_K21 + 512)           // f32 [4][64]
#define OFF_RINV (OFF_RED + 1024)          // f32 [64]
#define SMEM_BYTES (OFF_RINV + 256)        // 167168
#define OFF_CT   OFF_KS0                   // ctmp f32 [4][64][68] = 69632 B (fits in KS0+KS1)

__global__ __launch_bounds__(512, 1) void k_attn2(float* __restrict__ attn, int do_attn)
{
    extern __shared__ char smc[];
    float* Qs = (float*)(smc + OFF_QS);
    float* KsB[2] = { (float*)(smc + OFF_KS0), (float*)(smc + OFF_KS1) };
    __nv_bfloat16* VhB[2] = { (__nv_bfloat16*)(smc + OFF_VH0), (__nv_bfloat16*)(smc + OFF_VH1) };
    __nv_bfloat16* VlB[2] = { (__nv_bfloat16*)(smc + OFF_VL0), (__nv_bfloat16*)(smc + OFF_VL1) };
    float* k2B[2] = { (float*)(smc + OFF_K20), (float*)(smc + OFF_K21) };
    float* red  = (float*)(smc + OFF_RED);
    float* rinv = (float*)(smc + OFF_RINV);
    float* ctmp = (float*)(smc + OFF_CT);

    const int tid  = threadIdx.x;
    const int lane = tid & 31;
    const int wid  = tid >> 5;
    const int g    = lane >> 2;
    const int tig  = lane & 3;
    const int wm   = wid & 3;        // 4 m-tiles of 16 rows
    const int wn   = wid >> 2;       // 4 n/k quarters

    const int row0 = blockIdx.x * TQ;
    const int b    = row0 >> 11;
    const float* k_base  = g_k + (size_t)b * SEQ * HDIM;
    const __nv_bfloat16* vh_base = g_vth + (size_t)b * HDIM * SEQ;
    const __nv_bfloat16* vl_base = g_vtl + (size_t)b * HDIM * SEQ;
    const float* k2_base = g_k2 + b * SEQ;

    // ---- prologue staging ----
    #pragma unroll
    for (int it = 0; it < 2; it++) {                  // Q: 1024 x 16B
        int op = it * 512 + tid;
        int r = op >> 4, c = (op & 15) * 4;
        cpa16(&Qs[r * 68 + c], &g_q[(size_t)(row0 + r) * HDIM + c]);
    }
    #pragma unroll
    for (int it = 0; it < 4; it++) {                  // K: 2048 x 16B
        int op = it * 512 + tid;
        int r = op >> 4, c = (op & 15) * 4;
        cpa16(&KsB[0][r * 76 + c], k_base + (size_t)r * HDIM + c);
    }
    #pragma unroll
    for (int it = 0; it < 2; it++) {                  // Vh,Vl: 1024 x 16B each
        int op = it * 512 + tid;
        int h = op >> 4, ch = (op & 15) * 8;          // 8 bf16 = 16B
        cpa16(&VhB[0][h * 136 + ch], vh_base + (size_t)h * SEQ + ch);
        cpa16(&VlB[0][h * 136 + ch], vl_base + (size_t)h * SEQ + ch);
    }
    if (tid < 32) cpa16(&k2B[0][tid * 4], k2_base + tid * 4);
    CP_COMMIT();

    float q2r0 = g_q2[row0 + wm * 16 + g];
    float q2r1 = g_q2[row0 + wm * 16 + g + 8];

    float rs0 = 0.f, rs1 = 0.f;
    float cacc[8][4];
    #pragma unroll
    for (int i = 0; i < 8; i++)
        #pragma unroll
        for (int j = 0; j < 4; j++) cacc[i][j] = 0.f;

    for (int kb = 0; kb < NKB; kb++) {
        const int bf = kb & 1;
        if (kb + 1 < NKB) {
            const int nb = (kb + 1) & 1;
            const float* kn = k_base + (size_t)(kb + 1) * KT * HDIM;
            const __nv_bfloat16* vhn = vh_base + (kb + 1) * KT;
            const __nv_bfloat16* vln = vl_base + (kb + 1) * KT;
            #pragma unroll
            for (int it = 0; it < 4; it++) {
                int op = it * 512 + tid;
                int r = op >> 4, c = (op & 15) * 4;
                cpa16(&KsB[nb][r * 76 + c], kn + (size_t)r * HDIM + c);
            }
            #pragma unroll
            for (int it = 0; it < 2; it++) {
                int op = it * 512 + tid;
                int h = op >> 4, ch = (op & 15) * 8;
                cpa16(&VhB[nb][h * 136 + ch], vhn + (size_t)h * SEQ + ch);
                cpa16(&VlB[nb][h * 136 + ch], vln + (size_t)h * SEQ + ch);
            }
            if (tid < 32) cpa16(&k2B[nb][tid * 4], k2_base + (kb + 1) * KT + tid * 4);
            CP_COMMIT();
            CP_WAIT(1);
        } else {
            CP_WAIT(0);
        }
        __syncthreads();

        const float* Ks  = KsB[bf];
        const __nv_bfloat16* Vh = VhB[bf];
        const __nv_bfloat16* Vl = VlB[bf];
        const float* k2s = k2B[bf];

        // ---- scores (1x tf32): warp tile 16 x 32 (cols wn*32..+32) ----
        float e[4][4];
        #pragma unroll
        for (int nt = 0; nt < 4; nt++) {
            e[nt][0] = 0.f; e[nt][1] = 0.f; e[nt][2] = 0.f; e[nt][3] = 0.f;
        }
        #pragma unroll
        for (int kk = 0; kk < 8; kk++) {
            int ar = (wm * 16 + g) * 68 + kk * 8 + tig;
            float a0 = Qs[ar];
            float a1 = Qs[ar + 8 * 68];
            float a2 = Qs[ar + 4];
            float a3 = Qs[ar + 8 * 68 + 4];
            #pragma unroll
            for (int nt = 0; nt < 4; nt++) {
                int br = (wn * 32 + nt * 8 + g) * 76 + kk * 8 + tig;
                float b0 = Ks[br], b1 = Ks[br + 4];
                mma_tf32(e[nt][0], e[nt][1], e[nt][2], e[nt][3], a0, a1, a2, a3, b0, b1);
            }
        }

        // ---- exp in place + rowsum partial + attn store ----
        #pragma unroll
        for (int nt = 0; nt < 4; nt++) {
            int cg = wn * 32 + nt * 8 + 2 * tig;
            float2 k2p = *(const float2*)&k2s[cg];
            float e00 = __expf(-0.125f * (q2r0 + k2p.x - 2.f * e[nt][0]));
            float e01 = __expf(-0.125f * (q2r0 + k2p.y - 2.f * e[nt][1]));
            float e10 = __expf(-0.125f * (q2r1 + k2p.x - 2.f * e[nt][2]));
            float e11 = __expf(-0.125f * (q2r1 + k2p.y - 2.f * e[nt][3]));
            e[nt][0] = e00; e[nt][1] = e01; e[nt][2] = e10; e[nt][3] = e11;
            rs0 += e00 + e01;
            rs1 += e10 + e11;
            if (do_attn) {
                size_t a0i = (size_t)(row0 + wm * 16 + g) * SEQ + kb * KT + cg;
                *(float2*)&attn[a0i]           = make_float2(e00, e01);
                *(float2*)&attn[a0i + 8 * SEQ] = make_float2(e10, e11);
            }
        }

        // ---- ctx (3x bf16 m16n8k16): A directly from score accumulators ----
        #pragma unroll
        for (int c2 = 0; c2 < 2; c2++) {
            uint32_t ah0, ah1, ah2, ah3, al0, al1, al2, al3;
            split_bf(e[2*c2][0],   e[2*c2][1],   ah0, al0);   // row g,   k-cols 2tig..+1
            split_bf(e[2*c2][2],   e[2*c2][3],   ah1, al1);   // row g+8
            split_bf(e[2*c2+1][0], e[2*c2+1][1], ah2, al2);   // row g,   k-cols 2tig+8..+9
            split_bf(e[2*c2+1][2], e[2*c2+1][3], ah3, al3);   // row g+8
            int sb = wn * 32 + c2 * 16 + 2 * tig;             // k index within 128-tile
            #pragma unroll
            for (int nt = 0; nt < 8; nt++) {
                int vr = (nt * 8 + g) * 136 + sb;
                uint32_t bh0 = *(const uint32_t*)&Vh[vr];
                uint32_t bh1 = *(const uint32_t*)&Vh[vr + 8];
                uint32_t bl0 = *(const uint32_t*)&Vl[vr];
                uint32_t bl1 = *(const uint32_t*)&Vl[vr + 8];
                mma_bf16(cacc[nt], ah0, ah1, ah2, ah3, bh0, bh1);
                mma_bf16(cacc[nt], al0, al1, al2, al3, bh0, bh1);
                mma_bf16(cacc[nt], ah0, ah1, ah2, ah3, bl0, bl1);
            }
        }
        __syncthreads();
    }

    // ---- rowsum reduce (4 wn quarters per row) -> rinv ----
    rs0 += __shfl_xor_sync(0xffffffffu, rs0, 1);
    rs0 += __shfl_xor_sync(0xffffffffu, rs0, 2);
    rs1 += __shfl_xor_sync(0xffffffffu, rs1, 1);
    rs1 += __shfl_xor_sync(0xffffffffu, rs1, 2);
    if (tig == 0) {
        red[wn * 64 + wm * 16 + g]     = rs0;
        red[wn * 64 + wm * 16 + g + 8] = rs1;
    }
    __syncthreads();
    if (tid < 64)
        rinv[tid] = 1.0f / (red[tid] + red[64 + tid] + red[128 + tid] + red[192 + tid]);
    __syncthreads();   // all K/V reads complete before ctmp aliasing

    // ---- combine ctx quarters via ctmp (aliased over dead K smem) ----
    #pragma unroll
    for (int nt = 0; nt < 8; nt++) {
        int c = nt * 8 + 2 * tig;
        *(float2*)&ctmp[wn * 64 * 68 + (wm * 16 + g) * 68 + c]     = make_float2(cacc[nt][0], cacc[nt][1]);
        *(float2*)&ctmp[wn * 64 * 68 + (wm * 16 + g + 8) * 68 + c] = make_float2(cacc[nt][2], cacc[nt][3]);
    }
    __syncthreads();
    #pragma unroll
    for (int it = 0; it < 8; it++) {
        int idx = it * 512 + tid;
        int r = idx >> 6, c = idx & 63;
        float s = ctmp[r * 68 + c] + ctmp[64 * 68 + r * 68 + c]
                + ctmp[2 * 64 * 68 + r * 68 + c] + ctmp[3 * 64 * 68 + r * 68 + c];
        g_ctx[(size_t)(row0 + r) * HDIM + c] = s * rinv[r];
    }

    // ---- normalize attn in place ----
    if (do_attn) {
        for (int kb = 0; kb < NKB; kb++) {
            #pragma unroll
            for (int it = 0; it < 4; it++) {
                int f = it * 512 + tid;
                int r = f >> 5, c4 = (f & 31) * 4;
                float ri = rinv[r];
                float* p = &attn[(size_t)(row0 + r) * SEQ + kb * KT + c4];
                float4 v4 = *(float4*)p;
                v4.x *= ri; v4.y *= ri; v4.z *= ri; v4.w *= ri;
                *(float4*)p = v4;
            }
        }
    }
}

// ============== out = ctx @ Wo + bo ==============
__global__ __launch_bounds__(256) void k_out(
    const float* __restrict__ Wo, const float* __restrict__ bo, float* __restrict__ out)
{
    __shared__ float cs[4][64];
    int tid = threadIdx.x;
    int r = tid >> 6, h = tid & 63;
    int row = blockIdx.x * 4 + r;
    cs[r][h] = g_ctx[(size_t)row * HDIM + h];
    __syncthreads();
    float o = bo[h];
    #pragma unroll 16
    for (int hp = 0; hp < HDIM; hp++) o += cs[r][hp] * Wo[hp * HDIM + h];
    out[(size_t)row * HDIM + h] = o;
}

// =========================== launch ===========================
extern "C" void kernel_launch(void* const* d_in, const int* in_sizes, int n_in,
                              void* d_out, int out_size)
{
    const float* qs = (const float*)d_in[0];
    const float* ks = (const float*)d_in[1];
    const float* vs = (const float*)d_in[2];
    const float* Wq = (const float*)d_in[3];
    const float* bq = (const float*)d_in[4];
    const float* Wk = (const float*)d_in[5];
    const float* bk = (const float*)d_in[6];
    const float* Wv = (const float*)d_in[7];
    const float* bv = (const float*)d_in[8];
    const float* Wo = (const float*)d_in[9];
    const float* bo = (const float*)d_in[10];

    const int OUTN = ROWS * HDIM;        // 524288
    const int ATTN = ROWS * SEQ;         // 16777216

    float* souts = nullptr;
    cudaGetSymbolAddress((void**)&souts, g_outs);

    float* outp; float* attnp;
    if (out_size >= OUTN + ATTN)      { outp = (float*)d_out; attnp = (float*)d_out + OUTN; }
    else if (out_size == ATTN)        { outp = souts;         attnp = (float*)d_out; }
    else                              { outp = (float*)d_out; attnp = nullptr; }

    cudaFuncSetAttribute(k_proj,  cudaFuncAttributeMaxDynamicSharedMemorySize, PJ_BYTES);
    cudaFuncSetAttribute(k_attn2, cudaFuncAttributeMaxDynamicSharedMemorySize, SMEM_BYTES);

    k_nop1<<<1, 32>>>();
    k_nop2<<<1, 32>>>();
    k_proj<<<dim3(ROWS / 64, 3), 256, PJ_BYTES>>>(qs, ks, vs, Wq, bq, Wk, bk, Wv, bv);
    k_attn2<<<ROWS / TQ, 512, SMEM_BYTES>>>(attnp ? attnp : (float*)d_out,
                                            attnp != nullptr ? 1 : 0);
    k_out<<<ROWS / 4, 256>>>(Wo, bo, outp);
}